// round 14
// baseline (speedup 1.0000x reference)
#include <cuda_runtime.h>
#include <cuda_fp16.h>
#include <math.h>
#include <stdint.h>

#define EPSV 1e-6f
#define LOSCALE 2048.0f
#define INV_LOSCALE 4.8828125e-4f

// ---- smem byte layout (172,544 B total; 1 CTA/SM) ----
#define SAH    0        // A hi: [64m][256k] fp16, 512B rows, byte^(16*(m&7))
#define SAL    32768    // A lo (scaled by 2048)
#define SWRING 65536    // 6 slots x 16KB (chunk: hi 8KB + lo 8KB)
#define SBIAS  163840   // 4KB: b1eff, b2, b3, b4 (256 f32 each)
#define SD     167936   // L5 staging D[64][18] f32 (4608B)
#define SM_TOTAL 172544

// ---- device scratch: pre-split, pre-swizzled fp16 weight images (lo x2048) ----
__device__ __align__(16) unsigned char g_W1img[32768];    // 2 chunks: [256n][16k] hi8K+lo8K
__device__ __align__(16) unsigned char g_W234img[786432]; // 48 chunks of 16KB (l*16+c)
__device__ __align__(16) unsigned char g_W5img[16384];    // [16n][256k] 512B rows, hi8K+lo8K
__device__ __align__(16) float g_latconst[256];

static __device__ __forceinline__ uint32_t smem_u32(const void* p){
    uint32_t a; asm("{ .reg .u64 t; cvta.to.shared.u64 t, %1; cvt.u32.u64 %0, t; }":"=r"(a):"l"(p)); return a;
}
static __device__ __forceinline__ void cp16(uint32_t d, const void* s){
    asm volatile("cp.async.cg.shared.global [%0], [%1], 16;"::"r"(d),"l"(s));
}
#define CP_COMMIT() asm volatile("cp.async.commit_group;":::"memory")
#define CP_WAIT0()  asm volatile("cp.async.wait_group 0;":::"memory")
#define CP_WAIT4()  asm volatile("cp.async.wait_group 4;":::"memory")

static __device__ __forceinline__ void mma16816(float* c, uint32_t a0, uint32_t a1, uint32_t a2, uint32_t a3,
                                                uint32_t b0, uint32_t b1){
    asm volatile("mma.sync.aligned.m16n8k16.row.col.f32.f16.f16.f32 "
                 "{%0,%1,%2,%3},{%4,%5,%6,%7},{%8,%9},{%0,%1,%2,%3};"
                 : "+f"(c[0]),"+f"(c[1]),"+f"(c[2]),"+f"(c[3])
                 : "r"(a0),"r"(a1),"r"(a2),"r"(a3),"r"(b0),"r"(b1));
}
// fp16-accumulate variant (corrections only)
static __device__ __forceinline__ void mma16816h(uint32_t* c, uint32_t a0, uint32_t a1, uint32_t a2, uint32_t a3,
                                                 uint32_t b0, uint32_t b1){
    asm volatile("mma.sync.aligned.m16n8k16.row.col.f16.f16.f16.f16 "
                 "{%0,%1},{%2,%3,%4,%5},{%6,%7},{%0,%1};"
                 : "+r"(c[0]),"+r"(c[1])
                 : "r"(a0),"r"(a1),"r"(a2),"r"(a3),"r"(b0),"r"(b1));
}
static __device__ __forceinline__ float gelu_fast(float x){
    float z = fabsf(x)*0.70710678118654752f;
    float tt = __fdividef(1.0f, fmaf(0.3275911f, z, 1.0f));
    float poly = fmaf(fmaf(fmaf(fmaf(1.061405429f,tt,-1.453152027f),tt,1.421413741f),tt,-0.284496736f),tt,0.254829592f)*tt;
    float e = fmaf(-poly, __expf(-z*z), 1.0f);
    return 0.5f*x*(1.0f + copysignf(e, x));
}
// split into hi + lo*2048 (both fp16), packed as half2 words for columns (a,b)
static __device__ __forceinline__ void pack_split(float a, float b, uint32_t &ph, uint32_t &pl){
    __half ha = __float2half_rn(a), hb = __float2half_rn(b);
    __half la = __float2half_rn((a - __half2float(ha)) * LOSCALE);
    __half lb = __float2half_rn((b - __half2float(hb)) * LOSCALE);
    __half2 H = __halves2half2(ha,hb), L = __halves2half2(la,lb);
    ph = *(uint32_t*)&H; pl = *(uint32_t*)&L;
}

// ---------------- prep kernels ----------------
__global__ void latconst_kernel(const float* __restrict__ emb, const int* __restrict__ traj,
                                const float* __restrict__ W1, const float* __restrict__ b1){
    int n = threadIdx.x;
    const float* e = emb + (size_t)traj[0]*128;
    float s = b1[n];
#pragma unroll 4
    for (int j = 0; j < 128; ++j) s = fmaf(e[j], W1[(size_t)(25+j)*256+n], s);
    g_latconst[n] = s;
}

__global__ void prep_weights(const float* __restrict__ W1, const float* __restrict__ W2,
                             const float* __restrict__ W3, const float* __restrict__ W4,
                             const float* __restrict__ W5){
    int i = blockIdx.x*256 + threadIdx.x;            // 816 x 256 = 208896
    float v; unsigned char* dst; size_t off; int lo_delta;
    if (i < 196608) {                                // W2/3/4 -> k16 chunks, 32B rows
        int l = i / 65536, r = i % 65536, k = r >> 8, n = r & 255;
        const float* W = (l==0)?W2:(l==1)?W3:W4;
        v = W[(size_t)k*256+n];
        off = (size_t)(l*16 + (k>>4))*16384u + (size_t)n*32u
            + (size_t)(((uint32_t)(2*(k&15))) ^ (((uint32_t)n&4u)<<2));
        dst = g_W234img; lo_delta = 8192;
    } else if (i < 204800) {                         // W1: k<32 (pad>=25), 2 chunks
        int r = i-196608, n = r>>5, k = r&31;
        v = (k<25)? W1[(size_t)k*256+n] : 0.0f;
        off = (size_t)(k>>4)*16384u + (size_t)n*32u
            + (size_t)(((uint32_t)(2*(k&15))) ^ (((uint32_t)n&4u)<<2));
        dst = g_W1img; lo_delta = 8192;
    } else if (i < 208896) {                         // W5: [16n][256k] pad n>=9, 512B rows
        int r = i-204800, k = r>>4, n = r&15;
        v = (n<9)? W5[(size_t)k*9+n] : 0.0f;
        off = (size_t)n*512u + (size_t)(((uint32_t)(2*k)) ^ (((uint32_t)n&7u)<<4));
        dst = g_W5img; lo_delta = 8192;
    } else return;
    __half h = __float2half_rn(v);
    __half l = __float2half_rn((v - __half2float(h)) * LOSCALE);
    *(__half*)(dst + off) = h;
    *(__half*)(dst + off + lo_delta) = l;
}

// ---------------- chunk streaming ----------------
static __device__ __forceinline__ void issue_u(uint32_t smb, int t, int u){
    if (u > 50) return;
    const unsigned char* s = (u < 2)  ? g_W1img + (size_t)u*16384
                           : (u < 50) ? g_W234img + (size_t)(u-2)*16384
                                      : g_W5img;
    uint32_t dst = smb + SWRING + (uint32_t)(u % 6)*16384u + (uint32_t)t*16u;
    const unsigned char* sp = s + (size_t)t*16;
#pragma unroll
    for (int i = 0; i < 4; ++i) cp16(dst + (uint32_t)i*4096u, sp + (size_t)i*4096);
}

// one k16 chunk: main product -> fp32 acc; corrections -> fp16 acc
static __device__ __forceinline__ void compute_chunk(const char* sm, int slot, int c,
        int wm, int wn, int g, int tig, float (&acc)[2][8][4], uint32_t (&accc)[2][8][2]){
    const uint32_t gx = (uint32_t)g << 4;
    const uint32_t wx = ((uint32_t)g & 4u) << 2;
    const int kb = c*32 + 4*tig;
    const uint32_t k0A = (uint32_t)kb ^ gx, k1A = (uint32_t)(kb+16) ^ gx;
    const uint32_t k0W = ((uint32_t)(4*tig)) ^ wx, k1W = ((uint32_t)(4*tig+16)) ^ wx;
    uint32_t ah[2][4], al[2][4];
#pragma unroll
    for (int mt=0; mt<2; ++mt){
        const char* abh = sm + SAH + (wm*32 + g + mt*16)*512;
        const char* abl = abh + (SAL - SAH);
        ah[mt][0]=*(const uint32_t*)(abh+k0A); ah[mt][1]=*(const uint32_t*)(abh+4096+k0A);
        ah[mt][2]=*(const uint32_t*)(abh+k1A); ah[mt][3]=*(const uint32_t*)(abh+4096+k1A);
        al[mt][0]=*(const uint32_t*)(abl+k0A); al[mt][1]=*(const uint32_t*)(abl+4096+k0A);
        al[mt][2]=*(const uint32_t*)(abl+k1A); al[mt][3]=*(const uint32_t*)(abl+4096+k1A);
    }
    const char* wbase = sm + slot + (wn*64 + g)*32;
#pragma unroll
    for (int nt=0; nt<8; ++nt){
        const char* wbh = wbase + nt*256;
        const char* wbl = wbh + 8192;
        uint32_t bh0=*(const uint32_t*)(wbh+k0W), bh1=*(const uint32_t*)(wbh+k1W);
        uint32_t bl0=*(const uint32_t*)(wbl+k0W), bl1=*(const uint32_t*)(wbl+k1W);
#pragma unroll
        for (int mt=0; mt<2; ++mt){
            mma16816 (acc[mt][nt],  ah[mt][0],ah[mt][1],ah[mt][2],ah[mt][3], bh0,bh1);
            mma16816h(accc[mt][nt], ah[mt][0],ah[mt][1],ah[mt][2],ah[mt][3], bl0,bl1);
            mma16816h(accc[mt][nt], al[mt][0],al[mt][1],al[mt][2],al[mt][3], bh0,bh1);
        }
    }
}

static __device__ __forceinline__ void epilogue_layer(char* sm, int biasOff,
        int wm, int wn, int g, int tig, float (&acc)[2][8][4], uint32_t (&accc)[2][8][2]){
#pragma unroll
    for (int mt=0; mt<2; ++mt){
        char* rbh = sm + SAH + (wm*32 + g + mt*16)*512;
        char* rbl = rbh + (SAL - SAH);
        const uint32_t gx = (uint32_t)g << 4;
#pragma unroll
        for (int nt=0; nt<8; ++nt){
            int n0 = wn*64 + nt*8 + 2*tig;
            float2 bb = *(const float2*)(sm + biasOff + n0*4);
            float* c = acc[mt][nt];
            __half2 q0 = *(__half2*)&accc[mt][nt][0];   // corr c0,c1
            __half2 q1 = *(__half2*)&accc[mt][nt][1];   // corr c2,c3
            float x0 = c[0] + __low2float(q0)*INV_LOSCALE + bb.x;
            float x1 = c[1] + __high2float(q0)*INV_LOSCALE + bb.y;
            float x2 = c[2] + __low2float(q1)*INV_LOSCALE + bb.x;
            float x3 = c[3] + __high2float(q1)*INV_LOSCALE + bb.y;
            float y0 = gelu_fast(x0), y1 = gelu_fast(x1);
            float y2 = gelu_fast(x2), y3 = gelu_fast(x3);
            uint32_t kb2 = ((uint32_t)(n0*2)) ^ gx;
            uint32_t ph0,pl0,ph1,pl1;
            pack_split(y0,y1,ph0,pl0); pack_split(y2,y3,ph1,pl1);
            *(uint32_t*)(rbh + kb2)        = ph0;
            *(uint32_t*)(rbh + 4096 + kb2) = ph1;
            *(uint32_t*)(rbl + kb2)        = pl0;
            *(uint32_t*)(rbl + 4096 + kb2) = pl1;
        }
    }
}

// ---------------- main kernel: 64 particles / CTA, 256 threads ----------------
__global__ void __launch_bounds__(256, 1)
mlp_kernel(const float* __restrict__ Fg, const float* __restrict__ Cg,
           const float* __restrict__ b2, const float* __restrict__ b3,
           const float* __restrict__ b4, const float* __restrict__ b5,
           float* __restrict__ outg, int B){
    extern __shared__ char sm[];
    const uint32_t smb = smem_u32(sm);
    const int t = threadIdx.x, w = t>>5, lane = t&31;
    const int g = lane>>2, tig = lane&3;
    const int wm = w>>2, wn = w&3;
    const int g0 = blockIdx.x*64;

    // ---- prologue: chunks 0..3 as 4 groups; biases with group 0 ----
    issue_u(smb, t, 0);
    {
        const char* src;
        switch (t >> 6){
            case 0:  src = (const char*)g_latconst; break;
            case 1:  src = (const char*)b2; break;
            case 2:  src = (const char*)b3; break;
            default: src = (const char*)b4; break;
        }
        cp16(smb + SBIAS + (uint32_t)t*16u, src + (size_t)(t & 63)*16);
    }
    CP_COMMIT();
    issue_u(smb, t, 1); CP_COMMIT();
    issue_u(smb, t, 2); CP_COMMIT();
    issue_u(smb, t, 3); CP_COMMIT();

    // ---- phase 1: features into A + polar rotation in regs ----
    float R0=0,R1=0,R2=0,R3=0,R4=0,R5=0,R6=0,R7=0,R8=0;
    float F0=0,F1=0,F2=0,F3=0,F4=0,F5=0,F6=0,F7=0,F8=0;
    if (t < 64){
        int gp = g0 + t;
        float feat[25];
#pragma unroll
        for (int i=0;i<25;++i) feat[i]=0.0f;
        if (gp < B){
            const float* Fp = Fg + (size_t)gp*9;
            F0=Fp[0];F1=Fp[1];F2=Fp[2];F3=Fp[3];F4=Fp[4];F5=Fp[5];F6=Fp[6];F7=Fp[7];F8=Fp[8];
            float M00=F0*F0+F3*F3+F6*F6, M01=F0*F1+F3*F4+F6*F7, M02=F0*F2+F3*F5+F6*F8;
            float M11=F1*F1+F4*F4+F7*F7, M12=F1*F2+F4*F5+F7*F8, M22=F2*F2+F5*F5+F8*F8;
            float det = F0*(F4*F8-F5*F7) - F1*(F3*F8-F5*F6) + F2*(F3*F7-F4*F6);
            float q=(M00+M11+M22)*(1.0f/3.0f);
            float p1=M01*M01+M02*M02+M12*M12;
            float d0=M00-q,d1=M11-q,d2=M22-q;
            float p=sqrtf((d0*d0+d1*d1+d2*d2+2.0f*p1)*(1.0f/6.0f)+1e-30f);
            float ip=1.0f/p;
            float B00=d0*ip,B01=M01*ip,B02=M02*ip,B11=d1*ip,B12=M12*ip,B22=d2*ip;
            float detB=B00*(B11*B22-B12*B12)-B01*(B01*B22-B12*B02)+B02*(B01*B12-B11*B02);
            float rr=fminf(1.0f,fmaxf(-1.0f,0.5f*detB));
            float phi=acosf(rr)*(1.0f/3.0f);
            float e1=q+2.0f*p*cosf(phi);
            float e3=q+2.0f*p*cosf(phi+2.0943951023931953f);
            float e2=3.0f*q-e1-e3;
            float f00=fmaxf(F0,EPSV);
            feat[0]=sqrtf(fmaxf(e1,0.0f))-1.0f; feat[1]=sqrtf(fmaxf(e2,0.0f))-1.0f; feat[2]=sqrtf(fmaxf(e3,0.0f))-1.0f;
            feat[3]=M00-1.0f; feat[4]=M01; feat[5]=M02; feat[6]=M01; feat[7]=M11-1.0f; feat[8]=M12;
            feat[9]=M02; feat[10]=M12; feat[11]=M22-1.0f;
            feat[12]=det-1.0f; feat[13]=logf(det)-1.0f; feat[14]=f00-1.0f; feat[15]=logf(f00)-1.0f;
            const float* Cp = Cg + (size_t)gp*9;
#pragma unroll
            for (int i=0;i<9;++i) feat[16+i]=Cp[i];
            float X0=F0,X1=F1,X2=F2,X3=F3,X4=F4,X5=F5,X6=F6,X7=F7,X8=F8;
#pragma unroll
            for (int it=0; it<4; ++it){
                float C00=X4*X8-X5*X7, C01=-(X3*X8-X5*X6), C02=X3*X7-X4*X6;
                float C10=-(X1*X8-X2*X7), C11=X0*X8-X2*X6, C12=-(X0*X7-X1*X6);
                float C20=X1*X5-X2*X4, C21=-(X0*X5-X2*X3), C22=X0*X4-X1*X3;
                float h = 0.5f/(X0*C00+X1*C01+X2*C02);
                X0=0.5f*X0+C00*h; X1=0.5f*X1+C01*h; X2=0.5f*X2+C02*h;
                X3=0.5f*X3+C10*h; X4=0.5f*X4+C11*h; X5=0.5f*X5+C12*h;
                X6=0.5f*X6+C20*h; X7=0.5f*X7+C21*h; X8=0.5f*X8+C22*h;
            }
            R0=X0;R1=X1;R2=X2;R3=X3;R4=X4;R5=X5;R6=X6;R7=X7;R8=X8;
        }
        uint32_t mx = ((uint32_t)t & 7u) << 4;
        char* frh = sm + SAH + t*512;
        char* frl = sm + SAL + t*512;
#pragma unroll
        for (int j=0;j<16;++j){
            float x0 = (2*j   < 25)? feat[2*j]   : 0.0f;
            float x1 = (2*j+1 < 25)? feat[2*j+1] : 0.0f;
            uint32_t ph,pl; pack_split(x0,x1,ph,pl);
            *(uint32_t*)(frh + (((uint32_t)(4*j)) ^ mx)) = ph;
            *(uint32_t*)(frl + (((uint32_t)(4*j)) ^ mx)) = pl;
        }
    }

    // ---- layers 1..4: unified 50-chunk stream, depth-4 pipeline ----
    int u = 0;
#pragma unroll 1
    for (int L = 0; L < 4; ++L){
        const int nc = (L == 0) ? 2 : 16;
        float acc[2][8][4];
        uint32_t accc[2][8][2];
#pragma unroll
        for (int mt=0;mt<2;++mt)
#pragma unroll
            for (int nt=0;nt<8;++nt){
#pragma unroll
                for (int j=0;j<4;++j) acc[mt][nt][j]=0.0f;
                accc[mt][nt][0]=0u; accc[mt][nt][1]=0u;
            }
#pragma unroll 1
        for (int c = 0; c < nc; ++c, ++u){
            issue_u(smb, t, u+4);
            CP_COMMIT();
            CP_WAIT4();
            __syncthreads();
            compute_chunk(sm, SWRING + (u % 6)*16384, c, wm, wn, g, tig, acc, accc);
        }
        __syncthreads();                       // all reads of A done
        epilogue_layer(sm, SBIAS + L*1024, wm, wn, g, tig, acc, accc);
    }

    // ---- L5: chunk 50 (W5), warps 0..3, fp32 acc both (cost negligible) ----
    CP_WAIT0();
    __syncthreads();
    {
        const int slot = SWRING + (50 % 6)*16384;
        if (w < 4){
            float acc5m[2][4], acc5c[2][4];
#pragma unroll
            for (int nt=0;nt<2;++nt)
#pragma unroll
                for (int j=0;j<4;++j){ acc5m[nt][j]=0.0f; acc5c[nt][j]=0.0f; }
            int m0 = w*16 + g;
            const char* abh = sm + SAH + m0*512;
            const char* abl = sm + SAL + m0*512;
            uint32_t gx = (uint32_t)g<<4;
#pragma unroll
            for (int kc=0; kc<16; ++kc){
                int kb = kc*32 + 4*tig;
                uint32_t k0 = (uint32_t)kb ^ gx, k1 = (uint32_t)(kb+16) ^ gx;
                uint32_t ah0=*(const uint32_t*)(abh+k0), ah1=*(const uint32_t*)(abh+4096+k0);
                uint32_t ah2=*(const uint32_t*)(abh+k1), ah3=*(const uint32_t*)(abh+4096+k1);
                uint32_t al0=*(const uint32_t*)(abl+k0), al1=*(const uint32_t*)(abl+4096+k0);
                uint32_t al2=*(const uint32_t*)(abl+k1), al3=*(const uint32_t*)(abl+4096+k1);
#pragma unroll
                for (int nt=0; nt<2; ++nt){
                    const char* wbh = sm + slot + (nt*8+g)*512;
                    const char* wbl = wbh + 8192;
                    uint32_t bh0=*(const uint32_t*)(wbh+k0), bh1=*(const uint32_t*)(wbh+k1);
                    uint32_t bl0=*(const uint32_t*)(wbl+k0), bl1=*(const uint32_t*)(wbl+k1);
                    mma16816(acc5m[nt], ah0,ah1,ah2,ah3, bh0,bh1);
                    mma16816(acc5c[nt], ah0,ah1,ah2,ah3, bl0,bl1);
                    mma16816(acc5c[nt], al0,al1,al2,al3, bh0,bh1);
                }
            }
#pragma unroll
            for (int nt=0; nt<2; ++nt){
                int n0 = nt*8 + 2*tig;
                float v0 = acc5m[nt][0] + acc5c[nt][0]*INV_LOSCALE;
                float v1 = acc5m[nt][1] + acc5c[nt][1]*INV_LOSCALE;
                float v2 = acc5m[nt][2] + acc5c[nt][2]*INV_LOSCALE;
                float v3 = acc5m[nt][3] + acc5c[nt][3]*INV_LOSCALE;
                *(float2*)(sm + SD + ((size_t)m0*18 + n0)*4)     = make_float2(v0, v1);
                *(float2*)(sm + SD + ((size_t)(m0+8)*18 + n0)*4) = make_float2(v2, v3);
            }
        }
    }
    __syncthreads();

    // ---- final epilogue: symmetrize, P = R x, cauchy = P F^T ----
    if (t < 64){
        int gp = g0 + t;
        if (gp < B){
            const float* dr = (const float*)(sm + SD + (size_t)t*72);
            float o[9];
#pragma unroll
            for (int j=0;j<9;++j) o[j] = dr[j] + b5[j];
            float x00=o[0], x11=o[4], x22=o[8];
            float x01=0.5f*(o[1]+o[3]), x02=0.5f*(o[2]+o[6]), x12=0.5f*(o[5]+o[7]);
            float P00=R0*x00+R1*x01+R2*x02, P01=R0*x01+R1*x11+R2*x12, P02=R0*x02+R1*x12+R2*x22;
            float P10=R3*x00+R4*x01+R5*x02, P11=R3*x01+R4*x11+R5*x12, P12=R3*x02+R4*x12+R5*x22;
            float P20=R6*x00+R7*x01+R8*x02, P21=R6*x01+R7*x11+R8*x12, P22=R6*x02+R7*x12+R8*x22;
            float* op = outg + (size_t)gp*9;
            op[0]=P00*F0+P01*F1+P02*F2; op[1]=P00*F3+P01*F4+P02*F5; op[2]=P00*F6+P01*F7+P02*F8;
            op[3]=P10*F0+P11*F1+P12*F2; op[4]=P10*F3+P11*F4+P12*F5; op[5]=P10*F6+P11*F7+P12*F8;
            op[6]=P20*F0+P21*F1+P22*F2; op[7]=P20*F3+P21*F4+P22*F5; op[8]=P20*F6+P21*F7+P22*F8;
        }
    }
}

// ---------------------------------------------------------------------------
extern "C" void kernel_launch(void* const* d_in, const int* in_sizes, int n_in,
                              void* d_out, int out_size){
    const float* F   = (const float*)d_in[0];
    const float* C   = (const float*)d_in[1];
    const float* emb = (const float*)d_in[2];
    const int* traj  = (const int*)d_in[3];
    const float* W1 = (const float*)d_in[4];  const float* b1 = (const float*)d_in[5];
    const float* W2 = (const float*)d_in[6];  const float* b2 = (const float*)d_in[7];
    const float* W3 = (const float*)d_in[8];  const float* b3 = (const float*)d_in[9];
    const float* W4 = (const float*)d_in[10]; const float* b4 = (const float*)d_in[11];
    const float* W5 = (const float*)d_in[12]; const float* b5 = (const float*)d_in[13];
    int B = in_sizes[0] / 9;

    latconst_kernel<<<1, 256>>>(emb, traj, W1, b1);
    prep_weights<<<816, 256>>>(W1, W2, W3, W4, W5);

    cudaFuncSetAttribute(mlp_kernel, cudaFuncAttributeMaxDynamicSharedMemorySize, SM_TOTAL);
    int grid = (B + 63) / 64;
    mlp_kernel<<<grid, 256, SM_TOTAL>>>(F, C, b2, b3, b4, b5, (float*)d_out, B);
}